// round 5
// baseline (speedup 1.0000x reference)
#include <cuda_runtime.h>
#include <cstdint>

#define HW   512
#define NTHR 256
#define TPW  34
#define TPH  6
#define XS_CH (TPH * TPW)        // 204
#define TILES_PER_CTA 8
#define N_TILES 8192             // 4 * 16 * 128 tiles of 32x4

// smem layout (float offsets)
#define XS_OFF 0                          // 16*204 = 3264
#define YS_STR 132
#define YS_OFF 3264                       // 48*132 = 6336
#define H_STR  132
#define H_OFF  (YS_OFF + 48 * YS_STR)     // 9600 ; 64*132 = 8448
#define W0_OFF H_OFF                      // staging, aliased with H (6144 <= 8448)
#define W1_STR 132
#define W1_OFF (H_OFF + 64 * H_STR)       // 18048 ; 16*132 = 2112
#define B0_OFF (W1_OFF + 16 * W1_STR)     // 20160
#define MS_OFF (B0_OFF + 128)             // 20288
#define SM_FLOATS (MS_OFF + 128)          // 20416 floats = 81664 B

__device__ __forceinline__ float tf32f(float f) {
    uint32_t u;
    asm("cvt.rna.tf32.f32 %0, %1;" : "=r"(u) : "f"(f));
    return __uint_as_float(u);
}

// D += A(16x8) * B(8x8), tf32 inputs, f32 accumulate
__device__ __forceinline__ void mma8(float* d, const float* a, float b0, float b1) {
    asm("mma.sync.aligned.m16n8k8.row.col.f32.tf32.tf32.f32 "
        "{%0,%1,%2,%3}, {%4,%5,%6,%7}, {%8,%9}, {%0,%1,%2,%3};"
        : "+f"(d[0]), "+f"(d[1]), "+f"(d[2]), "+f"(d[3])
        : "r"(__float_as_uint(a[0])), "r"(__float_as_uint(a[1])),
          "r"(__float_as_uint(a[2])), "r"(__float_as_uint(a[3])),
          "r"(__float_as_uint(b0)), "r"(__float_as_uint(b1)));
}

__global__ __launch_bounds__(NTHR, 2)
void ca_mma_kernel(const float* __restrict__ x,
                   const float* __restrict__ w0,
                   const float* __restrict__ b0,
                   const float* __restrict__ w1,
                   const float* __restrict__ rand_u,
                   float* __restrict__ out)
{
    extern __shared__ float sm[];
    float* xs  = sm + XS_OFF;
    float* ys  = sm + YS_OFF;
    float* Hs  = sm + H_OFF;
    float* w0s = sm + W0_OFF;    // aliased with Hs (used only before tile loop)
    float* w1s = sm + W1_OFF;
    float* b0s = sm + B0_OFF;
    float* ms  = sm + MS_OFF;

    const int tid  = threadIdx.x;
    const int lane = tid & 31;
    const int wid  = tid >> 5;
    const int g    = lane >> 2;   // groupID
    const int t    = lane & 3;    // thread-in-group

    // ---- stage weights ----
    for (int i = tid; i < 128 * 48; i += NTHR) w0s[i] = tf32f(w0[i]);
    // W1 permuted: col c -> (c&7)*16 + (c>>3)  (k-fragment accesses become contiguous)
    for (int i = tid; i < 16 * 128; i += NTHR) {
        int r = i >> 7, c = i & 127;
        w1s[r * W1_STR + (c & 7) * 16 + (c >> 3)] = tf32f(w1[i]);
    }
    if (tid < 128) b0s[tid] = b0[tid];
    __syncthreads();

    // ---- persistent W0 A-fragments: warp wid owns hid rows [16*wid, 16*wid+16) ----
    float a1f[6][4];
    {
        const int r0 = 16 * wid + g;
        #pragma unroll
        for (int s = 0; s < 6; s++) {
            a1f[s][0] = w0s[r0 * 48 + 8 * s + t];
            a1f[s][1] = w0s[(r0 + 8) * 48 + 8 * s + t];
            a1f[s][2] = w0s[r0 * 48 + 8 * s + t + 4];
            a1f[s][3] = w0s[(r0 + 8) * 48 + 8 * s + t + 4];
        }
    }
    const float bias0 = b0s[16 * wid + g];
    const float bias1 = b0s[16 * wid + g + 8];

    // feature stage: thread q handles pixel p = ((q&15)<<3)|(q>>4), writes column q
    const int q    = tid & 127;
    const int fp   = ((q & 15) << 3) | (q >> 4);
    const int fpy  = fp >> 5, fpx = fp & 31;
    const int cb   = (tid >> 7) * 8;

    const int tile0 = blockIdx.x * TILES_PER_CTA;
    for (int it = 0; it < TILES_PER_CTA; ++it) {
        const int tile = tile0 + it;
        const int b    = tile >> 11;
        const int rem  = tile & 2047;
        const int gh0  = (rem >> 4) * 4;
        const int gw0  = (rem & 15) * 32;

        __syncthreads();   // protect xs/ms/Hs from previous iteration readers

        // ---- halo load (zero pad) + mask ----
        for (int i = tid; i < 16 * XS_CH; i += NTHR) {
            int c  = i / XS_CH;
            int r  = i % XS_CH;
            int hy = r / TPW, hx = r % TPW;
            int gh = gh0 + hy - 1, gw = gw0 + hx - 1;
            float v = 0.f;
            if (gh >= 0 && gh < HW && gw >= 0 && gw < HW)
                v = x[((size_t)(b * 16 + c) << 18) + (gh << 9) + gw];
            xs[i] = v;
        }
        if (tid < 128) {
            int gh = gh0 + (tid >> 5), gw = gw0 + (tid & 31);
            ms[tid] = rand_u[((size_t)b << 18) + (gh << 9) + gw] > 0.5f ? 1.f : 0.f;
        }
        __syncthreads();

        // ---- features: 8 channels for pixel fp -> permuted column q ----
        {
            #pragma unroll
            for (int c = 0; c < 8; c++) {
                const float* p = xs + (cb + c) * XS_CH + fpy * TPW + fpx;
                float a00 = p[0],       a01 = p[1],           a02 = p[2];
                float a10 = p[TPW],     a11 = p[TPW + 1],     a12 = p[TPW + 2];
                float a20 = p[2*TPW],   a21 = p[2*TPW + 1],   a22 = p[2*TPW + 2];
                float gx = (a02 - a00) + 2.f * (a12 - a10) + (a22 - a20);
                float gy = (a20 - a00) + 2.f * (a21 - a01) + (a22 - a02);
                ys[(cb + c) * YS_STR + q]      = tf32f(a11);
                ys[(16 + cb + c) * YS_STR + q] = tf32f(gx);
                ys[(32 + cb + c) * YS_STR + q] = tf32f(gy);
            }
        }
        __syncthreads();

        // ---- two 64-pixel passes ----
        #pragma unroll 1
        for (int sub = 0; sub < 2; sub++) {
            // GEMM1: warp's 16 hid rows x 64 permuted cols (q = n*16 + 8*sub + j)
            float acc[8][4];
            #pragma unroll
            for (int j = 0; j < 8; j++) {
                acc[j][0] = bias0; acc[j][1] = bias0;
                acc[j][2] = bias1; acc[j][3] = bias1;
            }
            #pragma unroll
            for (int s = 0; s < 6; s++) {
                const float4* pb0 = (const float4*)(ys + (8*s + t)     * YS_STR + g*16 + 8*sub);
                const float4* pb1 = (const float4*)(ys + (8*s + t + 4) * YS_STR + g*16 + 8*sub);
                float4 b0a = pb0[0], b0b = pb0[1];
                float4 b1a = pb1[0], b1b = pb1[1];
                mma8(acc[0], a1f[s], b0a.x, b1a.x);
                mma8(acc[1], a1f[s], b0a.y, b1a.y);
                mma8(acc[2], a1f[s], b0a.z, b1a.z);
                mma8(acc[3], a1f[s], b0a.w, b1a.w);
                mma8(acc[4], a1f[s], b0b.x, b1b.x);
                mma8(acc[5], a1f[s], b0b.y, b1b.y);
                mma8(acc[6], a1f[s], b0b.z, b1b.z);
                mma8(acc[7], a1f[s], b0b.w, b1b.w);
            }

            if (sub) __syncthreads();   // sub0 GEMM2 readers of Hs done

            // relu -> tf32 -> Hst[m][k_perm], m = n*8+j, k_perm(16w+g) = g*16+2w
            {
                const int col = g * 16 + 2 * wid;
                #pragma unroll
                for (int j = 0; j < 8; j++) {
                    float2 v0 = { tf32f(fmaxf(acc[j][0], 0.f)),
                                  tf32f(fmaxf(acc[j][2], 0.f)) };
                    float2 v1 = { tf32f(fmaxf(acc[j][1], 0.f)),
                                  tf32f(fmaxf(acc[j][3], 0.f)) };
                    *(float2*)(Hs + (16*t + j)     * H_STR + col) = v0;
                    *(float2*)(Hs + (16*t + 8 + j) * H_STR + col) = v1;
                }
            }
            __syncthreads();   // H ready

            // GEMM2: D2[16ch][8 cols m=8*wid..+7] = W1 * H
            float acc2[4] = {0.f, 0.f, 0.f, 0.f};
            {
                const float* wrg  = w1s + g * W1_STR;
                const float* wrg8 = w1s + (g + 8) * W1_STR;
                const float* hb   = Hs + (8 * wid + g) * H_STR;
                #pragma unroll
                for (int cph = 0; cph < 4; cph++) {
                    float4 A0 = *(const float4*)(wrg  + t*16       + 4*cph);
                    float4 A1 = *(const float4*)(wrg8 + t*16       + 4*cph);
                    float4 A2 = *(const float4*)(wrg  + (t+4)*16   + 4*cph);
                    float4 A3 = *(const float4*)(wrg8 + (t+4)*16   + 4*cph);
                    float4 Bv0 = *(const float4*)(hb + t*16     + 4*cph);
                    float4 Bv1 = *(const float4*)(hb + (t+4)*16 + 4*cph);
                    float aa[4];
                    aa[0] = A0.x; aa[1] = A1.x; aa[2] = A2.x; aa[3] = A3.x;
                    mma8(acc2, aa, Bv0.x, Bv1.x);
                    aa[0] = A0.y; aa[1] = A1.y; aa[2] = A2.y; aa[3] = A3.y;
                    mma8(acc2, aa, Bv0.y, Bv1.y);
                    aa[0] = A0.z; aa[1] = A1.z; aa[2] = A2.z; aa[3] = A3.z;
                    mma8(acc2, aa, Bv0.z, Bv1.z);
                    aa[0] = A0.w; aa[1] = A1.w; aa[2] = A2.w; aa[3] = A3.w;
                    mma8(acc2, aa, Bv0.w, Bv1.w);
                }
            }

            // epilogue: cols m=8w+2t,+1 -> pixels p0 = 64*sub+16*t+wid, p1 = p0+8
            {
                const int p0 = 64 * sub + 16 * t + wid;
                const int p1 = p0 + 8;
                const float m0 = ms[p0], m1 = ms[p1];
                const int py  = p0 >> 5;
                const int px0 = p0 & 31, px1 = px0 + 8;   // px0 <= 23, same row
                const float* xr0 = xs + g * XS_CH + (py + 1) * TPW + 1;
                const float* xr1 = xs + (g + 8) * XS_CH + (py + 1) * TPW + 1;
                const size_t rowoff = ((size_t)(gh0 + py) << 9) + gw0;
                size_t ob0 = ((size_t)(b * 16 + g)     << 18) + rowoff;
                size_t ob1 = ((size_t)(b * 16 + g + 8) << 18) + rowoff;
                out[ob0 + px0] = xr0[px0] + acc2[0] * m0;
                out[ob0 + px1] = xr0[px1] + acc2[1] * m1;
                out[ob1 + px0] = xr1[px0] + acc2[2] * m0;
                out[ob1 + px1] = xr1[px1] + acc2[3] * m1;
            }
        }
    }
}

extern "C" void kernel_launch(void* const* d_in, const int* in_sizes, int n_in,
                              void* d_out, int out_size)
{
    const float* x      = (const float*)d_in[0];
    const float* w0     = (const float*)d_in[1];
    const float* b0     = (const float*)d_in[2];
    const float* w1     = (const float*)d_in[3];
    const float* rand_u = (const float*)d_in[4];
    float* out = (float*)d_out;

    const int smem_bytes = SM_FLOATS * sizeof(float);   // 81664 B
    cudaFuncSetAttribute(ca_mma_kernel, cudaFuncAttributeMaxDynamicSharedMemorySize,
                         smem_bytes);
    dim3 grid(N_TILES / TILES_PER_CTA);  // 1024 CTAs
    ca_mma_kernel<<<grid, NTHR, smem_bytes>>>(x, w0, b0, w1, rand_u, out);
}

// round 8
// speedup vs baseline: 1.7833x; 1.7833x over previous
#include <cuda_runtime.h>
#include <cstdint>

#define HW   512
#define NTHR 256
#define TPW  34
#define TPH  6
#define XS_CH (TPH * TPW)        // 204
#define TILES_PER_CTA 8
#define N_TILES 8192             // 4 batches * 16 * 128 tiles of 32x4

// smem layout (float offsets)
// Region at YS_OFF is time-shared: w0 staging (startup) -> per tile: ys (features),
// then H (after GEMM1 ys-reads complete, protected by a barrier).
#define XS_OFF 0                 // [16][204] = 3264
#define YS_STR 136
#define YS_OFF 3264              // ys: [48][136] = 6528
#define H_STR  136
#define H_OFF  3264              // H: [128][136] used cols 0..127 -> 17408
#define W0_OFF 3264              // staging only (6144 <= 17408)
#define REGION 17408
#define W1_STR 132
#define W1_OFF (YS_OFF + REGION)        // 20672 ; [16][132] = 2112
#define B0_OFF (W1_OFF + 2112)          // 22784
#define MS_OFF (B0_OFF + 128)           // 22912
#define SM_FLOATS (MS_OFF + 128)        // 23040 floats = 92160 B

__device__ __forceinline__ float tf32f(float f) {
    uint32_t u;
    asm("cvt.rna.tf32.f32 %0, %1;" : "=r"(u) : "f"(f));
    return __uint_as_float(u);
}

// D += A(16x8) * B(8x8), tf32 inputs, f32 accumulate
__device__ __forceinline__ void mma8(float* d, const float* a, float b0, float b1) {
    asm("mma.sync.aligned.m16n8k8.row.col.f32.tf32.tf32.f32 "
        "{%0,%1,%2,%3}, {%4,%5,%6,%7}, {%8,%9}, {%0,%1,%2,%3};"
        : "+f"(d[0]), "+f"(d[1]), "+f"(d[2]), "+f"(d[3])
        : "r"(__float_as_uint(a[0])), "r"(__float_as_uint(a[1])),
          "r"(__float_as_uint(a[2])), "r"(__float_as_uint(a[3])),
          "r"(__float_as_uint(b0)), "r"(__float_as_uint(b1)));
}

__global__ __launch_bounds__(NTHR, 2)
void ca_mma_kernel(const float* __restrict__ x,
                   const float* __restrict__ w0,
                   const float* __restrict__ b0,
                   const float* __restrict__ w1,
                   const float* __restrict__ rand_u,
                   float* __restrict__ out)
{
    extern __shared__ float sm[];
    float* xs  = sm + XS_OFF;
    float* ys  = sm + YS_OFF;
    float* Hs  = sm + H_OFF;
    float* w0s = sm + W0_OFF;   // startup staging, aliased
    float* w1s = sm + W1_OFF;
    float* b0s = sm + B0_OFF;
    float* ms  = sm + MS_OFF;

    const int tid  = threadIdx.x;
    const int lane = tid & 31;
    const int wid  = tid >> 5;
    const int g    = lane >> 2;   // groupID
    const int t    = lane & 3;    // thread-in-group

    // ---- stage weights (tf32-rounded) ----
    for (int i = tid; i < 128 * 48; i += NTHR) w0s[i] = tf32f(w0[i]);
    for (int i = tid; i < 16 * 128; i += NTHR) {
        int r = i >> 7, c = i & 127;
        w1s[r * W1_STR + c] = tf32f(w1[i]);
    }
    if (tid < 128) b0s[tid] = b0[tid];
    __syncthreads();

    // ---- persistent W0 A-fragments: warp wid owns hid rows [16*wid, 16*wid+16) ----
    float a1f[6][4];
    {
        const int r0 = 16 * wid + g;
        #pragma unroll
        for (int s = 0; s < 6; s++) {
            a1f[s][0] = w0s[r0 * 48 + 8 * s + t];
            a1f[s][1] = w0s[(r0 + 8) * 48 + 8 * s + t];
            a1f[s][2] = w0s[r0 * 48 + 8 * s + t + 4];
            a1f[s][3] = w0s[(r0 + 8) * 48 + 8 * s + t + 4];
        }
    }
    const float bias0 = b0s[16 * wid + g];
    const float bias1 = b0s[16 * wid + g + 8];

    const int px_  = tid & 127;          // feature pixel for this thread
    const int fsel = tid >> 7;           // which 8 channels
    const int fpy  = px_ >> 5, fpx = px_ & 31;

    const int tile0 = blockIdx.x * TILES_PER_CTA;
    for (int it = 0; it < TILES_PER_CTA; ++it) {
        const int tile = tile0 + it;
        const int b    = tile >> 11;
        const int rem  = tile & 2047;
        const int gh0  = (rem >> 4) * 4;
        const int gw0  = (rem & 15) * 32;

        __syncthreads();   // prev tile's readers of xs/ms/Hs done

        // ---- halo load (zero pad) + mask ----
        for (int i = tid; i < 16 * XS_CH; i += NTHR) {
            int c  = i / XS_CH;
            int r  = i % XS_CH;
            int hy = r / TPW, hx = r % TPW;
            int gh = gh0 + hy - 1, gw = gw0 + hx - 1;
            float v = 0.f;
            if (gh >= 0 && gh < HW && gw >= 0 && gw < HW)
                v = x[((size_t)(b * 16 + c) << 18) + (gh << 9) + gw];
            xs[i] = v;
        }
        if (tid < 128) {
            int gh = gh0 + (tid >> 5), gw = gw0 + (tid & 31);
            ms[tid] = rand_u[((size_t)b << 18) + (gh << 9) + gw] > 0.5f ? 1.f : 0.f;
        }
        __syncthreads();

        // ---- features: this thread does 8 channels for pixel px_ ----
        {
            const int cb = fsel * 8;
            #pragma unroll
            for (int c = 0; c < 8; c++) {
                const float* p = xs + (cb + c) * XS_CH + fpy * TPW + fpx;
                float a00 = p[0],       a01 = p[1],           a02 = p[2];
                float a10 = p[TPW],     a11 = p[TPW + 1],     a12 = p[TPW + 2];
                float a20 = p[2*TPW],   a21 = p[2*TPW + 1],   a22 = p[2*TPW + 2];
                float gx = (a02 - a00) + 2.f * (a12 - a10) + (a22 - a20);
                float gy = (a20 - a00) + 2.f * (a21 - a01) + (a22 - a02);
                ys[(cb + c) * YS_STR + px_]      = tf32f(a11);
                ys[(16 + cb + c) * YS_STR + px_] = tf32f(gx);
                ys[(32 + cb + c) * YS_STR + px_] = tf32f(gy);
            }
        }
        __syncthreads();

        // ---- GEMM1 for BOTH 64-px halves (exact R4 indices, looped over sub) ----
        float acc[2][8][4];
        #pragma unroll
        for (int sub = 0; sub < 2; sub++) {
            const int pxb = sub * 64;
            #pragma unroll
            for (int j = 0; j < 8; j++) {
                acc[sub][j][0] = bias0; acc[sub][j][1] = bias0;
                acc[sub][j][2] = bias1; acc[sub][j][3] = bias1;
            }
            #pragma unroll
            for (int s = 0; s < 6; s++) {
                const float* yb0 = ys + (8 * s + t) * YS_STR + pxb + g;
                const float* yb1 = ys + (8 * s + t + 4) * YS_STR + pxb + g;
                #pragma unroll
                for (int j = 0; j < 8; j++)
                    mma8(acc[sub][j], a1f[s], yb0[8 * j], yb1[8 * j]);
            }
        }
        __syncthreads();   // all ys reads done; region becomes H

        // ---- relu -> tf32 -> H[hid][128]  (R4 store statements + 64*sub col shift) ----
        {
            const int hr = 16 * wid + g;
            #pragma unroll
            for (int sub = 0; sub < 2; sub++) {
                #pragma unroll
                for (int j = 0; j < 8; j++) {
                    int cc = 64 * sub + 8 * j + 2 * t;
                    Hs[hr * H_STR + cc]           = tf32f(fmaxf(acc[sub][j][0], 0.f));
                    Hs[hr * H_STR + cc + 1]       = tf32f(fmaxf(acc[sub][j][1], 0.f));
                    Hs[(hr + 8) * H_STR + cc]     = tf32f(fmaxf(acc[sub][j][2], 0.f));
                    Hs[(hr + 8) * H_STR + cc + 1] = tf32f(fmaxf(acc[sub][j][3], 0.f));
                }
            }
        }
        __syncthreads();   // H ready

        // ---- GEMM2 + epilogue per half (GEMM2 = R4 + 64*sub; epilogue = R4 EXACT) ----
        #pragma unroll
        for (int sub = 0; sub < 2; sub++) {
            float acc2[4] = {0.f, 0.f, 0.f, 0.f};
            #pragma unroll
            for (int s = 0; s < 16; s++) {
                float aa[4];
                aa[0] = w1s[g * W1_STR + 8 * s + t];
                aa[1] = w1s[(g + 8) * W1_STR + 8 * s + t];
                aa[2] = w1s[g * W1_STR + 8 * s + t + 4];
                aa[3] = w1s[(g + 8) * W1_STR + 8 * s + t + 4];
                float bb0 = Hs[(8 * s + t) * H_STR + 64 * sub + 8 * wid + g];
                float bb1 = Hs[(8 * s + t + 4) * H_STR + 64 * sub + 8 * wid + g];
                mma8(acc2, aa, bb0, bb1);
            }

            // R4's epilogue, verbatim (pxb = 64*sub):
            {
                const int cl = 8 * wid + 2 * t;      // chunk-local col (even)
                const int p  = 64 * sub + cl;        // pixel 0..126 (even)
                const int py = p >> 5, pxw = p & 31;
                const float m0 = ms[p], m1 = ms[p + 1];
                const int ch = g, ch2 = g + 8;
                const float* xc0 = xs + ch  * XS_CH + (py + 1) * TPW + pxw + 1;
                const float* xc1 = xs + ch2 * XS_CH + (py + 1) * TPW + pxw + 1;
                size_t o0 = ((size_t)(b * 16 + ch)  << 18) + ((size_t)(gh0 + py) << 9) + gw0 + pxw;
                size_t o1 = ((size_t)(b * 16 + ch2) << 18) + ((size_t)(gh0 + py) << 9) + gw0 + pxw;
                float2 v0 = { xc0[0] + acc2[0] * m0, xc0[1] + acc2[1] * m1 };
                float2 v1 = { xc1[0] + acc2[2] * m0, xc1[1] + acc2[3] * m1 };
                *(float2*)(out + o0) = v0;
                *(float2*)(out + o1) = v1;
            }
        }
    }
}

extern "C" void kernel_launch(void* const* d_in, const int* in_sizes, int n_in,
                              void* d_out, int out_size)
{
    const float* x      = (const float*)d_in[0];
    const float* w0     = (const float*)d_in[1];
    const float* b0     = (const float*)d_in[2];
    const float* w1     = (const float*)d_in[3];
    const float* rand_u = (const float*)d_in[4];
    float* out = (float*)d_out;

    const int smem_bytes = SM_FLOATS * sizeof(float);   // 92160 B
    cudaFuncSetAttribute(ca_mma_kernel, cudaFuncAttributeMaxDynamicSharedMemorySize,
                         smem_bytes);
    dim3 grid(N_TILES / TILES_PER_CTA);  // 1024 CTAs
    ca_mma_kernel<<<grid, NTHR, smem_bytes>>>(x, w0, b0, w1, rand_u, out);
}

// round 9
// speedup vs baseline: 2.1338x; 1.1965x over previous
#include <cuda_runtime.h>
#include <cstdint>

#define HW   512
#define NTHR 256
#define TPW  34
#define TPH  6
#define XS_CH (TPH * TPW)        // 204
#define TILES_PER_CTA 8
#define N_TILES 8192             // 4 batches * 16 * 128 tiles of 32x4

// smem layout (float offsets)
// Region at YS_OFF is time-shared: w0 staging (startup) -> per tile: ys (features),
// then H (after GEMM1 ys-reads complete, protected by a barrier).
#define XS_OFF 0                 // [16][204] = 3264
#define YS_STR 136
#define YS_OFF 3264              // ys: [48][136] = 6528
#define H_STR  136
#define H_OFF  3264              // H: [128][136] used cols 0..127 -> 17408
#define W0_OFF 3264              // staging only (6144 <= 17408)
#define REGION 17408
#define W1_STR 132
#define W1_OFF (YS_OFF + REGION)        // 20672 ; [16][132] = 2112
#define B0_OFF (W1_OFF + 2112)          // 22784
#define MS_OFF (B0_OFF + 128)           // 22912
#define SM_FLOATS (MS_OFF + 128)        // 23040 floats = 92160 B

__device__ __forceinline__ float tf32f(float f) {
    uint32_t u;
    asm("cvt.rna.tf32.f32 %0, %1;" : "=r"(u) : "f"(f));
    return __uint_as_float(u);
}

// D += A(16x8) * B(8x8), tf32 inputs, f32 accumulate
__device__ __forceinline__ void mma8(float* d, const float* a, float b0, float b1) {
    asm("mma.sync.aligned.m16n8k8.row.col.f32.tf32.tf32.f32 "
        "{%0,%1,%2,%3}, {%4,%5,%6,%7}, {%8,%9}, {%0,%1,%2,%3};"
        : "+f"(d[0]), "+f"(d[1]), "+f"(d[2]), "+f"(d[3])
        : "r"(__float_as_uint(a[0])), "r"(__float_as_uint(a[1])),
          "r"(__float_as_uint(a[2])), "r"(__float_as_uint(a[3])),
          "r"(__float_as_uint(b0)), "r"(__float_as_uint(b1)));
}

__global__ __launch_bounds__(NTHR, 2)
void ca_mma_kernel(const float* __restrict__ x,
                   const float* __restrict__ w0,
                   const float* __restrict__ b0,
                   const float* __restrict__ w1,
                   const float* __restrict__ rand_u,
                   float* __restrict__ out)
{
    extern __shared__ float sm[];
    float* xs  = sm + XS_OFF;
    float* ys  = sm + YS_OFF;
    float* Hs  = sm + H_OFF;
    float* w0s = sm + W0_OFF;   // startup staging, aliased
    float* w1s = sm + W1_OFF;
    float* b0s = sm + B0_OFF;
    float* ms  = sm + MS_OFF;

    const int tid  = threadIdx.x;
    const int lane = tid & 31;
    const int wid  = tid >> 5;
    const int g    = lane >> 2;   // groupID
    const int t    = lane & 3;    // thread-in-group

    // ---- stage weights (tf32-rounded) ----
    for (int i = tid; i < 128 * 48; i += NTHR) w0s[i] = tf32f(w0[i]);
    for (int i = tid; i < 16 * 128; i += NTHR) {
        int r = i >> 7, c = i & 127;
        w1s[r * W1_STR + c] = tf32f(w1[i]);
    }
    if (tid < 128) b0s[tid] = b0[tid];
    __syncthreads();

    // ---- persistent W0 A-fragments: warp wid owns hid rows [16*wid, 16*wid+16) ----
    float a1f[6][4];
    {
        const int r0 = 16 * wid + g;
        #pragma unroll
        for (int s = 0; s < 6; s++) {
            a1f[s][0] = w0s[r0 * 48 + 8 * s + t];
            a1f[s][1] = w0s[(r0 + 8) * 48 + 8 * s + t];
            a1f[s][2] = w0s[r0 * 48 + 8 * s + t + 4];
            a1f[s][3] = w0s[(r0 + 8) * 48 + 8 * s + t + 4];
        }
    }
    const float bias0 = b0s[16 * wid + g];
    const float bias1 = b0s[16 * wid + g + 8];

    const int px_  = tid & 127;          // feature pixel for this thread
    const int fsel = tid >> 7;           // which 8 channels
    const int fpy  = px_ >> 5, fpx = px_ & 31;

    // halo loader role: threads 0..203 each load 16 channels of one (hy,hx)
    const int hpos = tid;                // valid if < 204
    const int hhy  = hpos / TPW;
    const int hhx  = hpos - hhy * TPW;

    const int tile0 = blockIdx.x * TILES_PER_CTA;
    for (int it = 0; it < TILES_PER_CTA; ++it) {
        const int tile = tile0 + it;
        const int b    = tile >> 11;
        const int rem  = tile & 2047;
        const int gh0  = (rem >> 4) * 4;
        const int gw0  = (rem & 15) * 32;

        __syncthreads();   // prev tile's readers of xs/ms/Hs done

        // ---- halo load (zero pad): 204 workers x 16 channels ----
        if (hpos < XS_CH) {
            const int gh = gh0 + hhy - 1, gw = gw0 + hhx - 1;
            if (gh >= 0 && gh < HW && gw >= 0 && gw < HW) {
                const float* gp = x + (((size_t)b << 22)) + ((size_t)(gh << 9) + gw);
                #pragma unroll
                for (int c = 0; c < 16; c++)
                    xs[c * XS_CH + hpos] = gp[(size_t)c << 18];
            } else {
                #pragma unroll
                for (int c = 0; c < 16; c++)
                    xs[c * XS_CH + hpos] = 0.f;
            }
        }
        if (tid < 128) {
            int gh = gh0 + (tid >> 5), gw = gw0 + (tid & 31);
            ms[tid] = rand_u[((size_t)b << 18) + (gh << 9) + gw] > 0.5f ? 1.f : 0.f;
        }
        __syncthreads();

        // ---- features: this thread does 8 channels for pixel px_ ----
        {
            const int cb = fsel * 8;
            #pragma unroll
            for (int c = 0; c < 8; c++) {
                const float* p = xs + (cb + c) * XS_CH + fpy * TPW + fpx;
                float a00 = p[0],       a01 = p[1],           a02 = p[2];
                float a10 = p[TPW],     a11 = p[TPW + 1],     a12 = p[TPW + 2];
                float a20 = p[2*TPW],   a21 = p[2*TPW + 1],   a22 = p[2*TPW + 2];
                float gx = (a02 - a00) + 2.f * (a12 - a10) + (a22 - a20);
                float gy = (a20 - a00) + 2.f * (a21 - a01) + (a22 - a02);
                ys[(cb + c) * YS_STR + px_]      = tf32f(a11);
                ys[(16 + cb + c) * YS_STR + px_] = tf32f(gx);
                ys[(32 + cb + c) * YS_STR + px_] = tf32f(gy);
            }
        }
        __syncthreads();

        // ---- GEMM1 for BOTH 64-px halves (exact R4 indices, looped over sub) ----
        float acc[2][8][4];
        #pragma unroll
        for (int sub = 0; sub < 2; sub++) {
            const int pxb = sub * 64;
            #pragma unroll
            for (int j = 0; j < 8; j++) {
                acc[sub][j][0] = bias0; acc[sub][j][1] = bias0;
                acc[sub][j][2] = bias1; acc[sub][j][3] = bias1;
            }
            #pragma unroll
            for (int s = 0; s < 6; s++) {
                const float* yb0 = ys + (8 * s + t) * YS_STR + pxb + g;
                const float* yb1 = ys + (8 * s + t + 4) * YS_STR + pxb + g;
                #pragma unroll
                for (int j = 0; j < 8; j++)
                    mma8(acc[sub][j], a1f[s], yb0[8 * j], yb1[8 * j]);
            }
        }
        __syncthreads();   // all ys reads done; region becomes H

        // ---- relu -> tf32 -> H[hid][128] (same addrs as R8, float2-paired) ----
        {
            const int hr = 16 * wid + g;
            #pragma unroll
            for (int sub = 0; sub < 2; sub++) {
                #pragma unroll
                for (int j = 0; j < 8; j++) {
                    int cc = 64 * sub + 8 * j + 2 * t;
                    float2 v0 = { tf32f(fmaxf(acc[sub][j][0], 0.f)),
                                  tf32f(fmaxf(acc[sub][j][1], 0.f)) };
                    float2 v1 = { tf32f(fmaxf(acc[sub][j][2], 0.f)),
                                  tf32f(fmaxf(acc[sub][j][3], 0.f)) };
                    *(float2*)(Hs + hr * H_STR + cc)       = v0;
                    *(float2*)(Hs + (hr + 8) * H_STR + cc) = v1;
                }
            }
        }
        __syncthreads();   // H ready

        // ---- GEMM2: both halves in one k-loop (A fragments loaded once) ----
        float acc2[2][4] = {{0.f,0.f,0.f,0.f},{0.f,0.f,0.f,0.f}};
        #pragma unroll
        for (int s = 0; s < 16; s++) {
            float aa[4];
            aa[0] = w1s[g * W1_STR + 8 * s + t];
            aa[1] = w1s[(g + 8) * W1_STR + 8 * s + t];
            aa[2] = w1s[g * W1_STR + 8 * s + t + 4];
            aa[3] = w1s[(g + 8) * W1_STR + 8 * s + t + 4];
            const float* hb0 = Hs + (8 * s + t) * H_STR + 8 * wid + g;
            const float* hb1 = Hs + (8 * s + t + 4) * H_STR + 8 * wid + g;
            mma8(acc2[0], aa, hb0[0],  hb1[0]);
            mma8(acc2[1], aa, hb0[64], hb1[64]);
        }

        // ---- epilogue per half (R4 EXACT, pxb = 64*sub) ----
        #pragma unroll
        for (int sub = 0; sub < 2; sub++) {
            const int cl = 8 * wid + 2 * t;      // chunk-local col (even)
            const int p  = 64 * sub + cl;        // pixel 0..126 (even)
            const int py = p >> 5, pxw = p & 31;
            const float m0 = ms[p], m1 = ms[p + 1];
            const int ch = g, ch2 = g + 8;
            const float* xc0 = xs + ch  * XS_CH + (py + 1) * TPW + pxw + 1;
            const float* xc1 = xs + ch2 * XS_CH + (py + 1) * TPW + pxw + 1;
            size_t o0 = ((size_t)(b * 16 + ch)  << 18) + ((size_t)(gh0 + py) << 9) + gw0 + pxw;
            size_t o1 = ((size_t)(b * 16 + ch2) << 18) + ((size_t)(gh0 + py) << 9) + gw0 + pxw;
            float2 v0 = { xc0[0] + acc2[sub][0] * m0, xc0[1] + acc2[sub][1] * m1 };
            float2 v1 = { xc1[0] + acc2[sub][2] * m0, xc1[1] + acc2[sub][3] * m1 };
            *(float2*)(out + o0) = v0;
            *(float2*)(out + o1) = v1;
        }
    }
}

extern "C" void kernel_launch(void* const* d_in, const int* in_sizes, int n_in,
                              void* d_out, int out_size)
{
    const float* x      = (const float*)d_in[0];
    const float* w0     = (const float*)d_in[1];
    const float* b0     = (const float*)d_in[2];
    const float* w1     = (const float*)d_in[3];
    const float* rand_u = (const float*)d_in[4];
    float* out = (float*)d_out;

    const int smem_bytes = SM_FLOATS * sizeof(float);   // 92160 B
    cudaFuncSetAttribute(ca_mma_kernel, cudaFuncAttributeMaxDynamicSharedMemorySize,
                         smem_bytes);
    dim3 grid(N_TILES / TILES_PER_CTA);  // 1024 CTAs
    ca_mma_kernel<<<grid, NTHR, smem_bytes>>>(x, w0, b0, w1, rand_u, out);
}